// round 1
// baseline (speedup 1.0000x reference)
#include <cuda_runtime.h>

// Problem constants
#define C_   16
#define GX_  36
#define GY_  36
#define RF_  24
#define IMG_ 64
#define G_   (GX_ * GY_)        // 1296
#define GAMMA_E 0.9f
#define GAMMA_I 0.9f
#define THREADS_ 256

__global__ __launch_bounds__(THREADS_, 8)
void cortex_kernel(const float* __restrict__ x,
                   const float* __restrict__ prev,
                   const float* __restrict__ aw,
                   const float* __restrict__ ew,
                   const float* __restrict__ iw,
                   const int*   __restrict__ rx,
                   const int*   __restrict__ ry,
                   float*       __restrict__ out)
{
    const int ij = blockIdx.x;           // 0..1295
    const int i  = ij / GY_;
    const int j  = ij - i * GY_;
    const int t  = threadIdx.x;

    __shared__ float s_prev[C_];
    __shared__ int   s_rx, s_ry;
    if (t < C_) s_prev[t] = prev[t * G_ + ij];
    if (t == 0) { s_rx = rx[i]; s_ry = ry[j]; }
    __syncthreads();

    // ---- Lateral excitatory + inhibitory ----
    // exc = sum_c prev[c,ij] * sum_{xy} EW[c,ij,xy]   (same for inh)
    // Each (c,ij) row is 1296 contiguous floats = 324 float4, 16B-aligned.
    float exc = 0.f, inh = 0.f;
    const int NF4 = G_ / 4;              // 324
    #pragma unroll 4
    for (int e = t; e < C_ * NF4; e += THREADS_) {
        const int c = e / NF4;
        const int o = e - c * NF4;
        const float p = s_prev[c];
        const size_t rowbase = (size_t)(c * G_ + ij) * G_;
        const float4 ve = __ldg(reinterpret_cast<const float4*>(ew + rowbase) + o);
        const float4 vi = __ldg(reinterpret_cast<const float4*>(iw + rowbase) + o);
        exc += p * ((ve.x + ve.y) + (ve.z + ve.w));
        inh += p * ((vi.x + vi.y) + (vi.z + vi.w));
    }

    // ---- Afferent ----
    // aff = sum_{c,u,v} x[c, rx[i]+u, ry[j]+v] * AW[c,ij,u,v]
    // AW rows: 576 contiguous floats = 144 float4 per (c,ij). 24%4==0 so each
    // float4 stays within one u-row of the 24x24 patch.
    float aff = 0.f;
    const int AF4 = (RF_ * RF_) / 4;     // 144
    const int rxi = s_rx, ryj = s_ry;
    #pragma unroll
    for (int e = t; e < C_ * AF4; e += THREADS_) {   // 2304/256 = 9 iters
        const int c = e / AF4;
        const int o = e - c * AF4;
        const int uv = o * 4;
        const int u  = uv / RF_;
        const int v  = uv - u * RF_;
        const float4 w4 = __ldg(reinterpret_cast<const float4*>(
                              aw + (size_t)(c * G_ + ij) * (RF_ * RF_)) + o);
        const float* xr = x + c * IMG_ * IMG_ + (rxi + u) * IMG_ + (ryj + v);
        aff += w4.x * __ldg(xr + 0) + w4.y * __ldg(xr + 1)
             + w4.z * __ldg(xr + 2) + w4.w * __ldg(xr + 3);
    }

    // ---- Block reduction of (aff, exc, inh) ----
    const unsigned FULL = 0xFFFFFFFFu;
    #pragma unroll
    for (int off = 16; off > 0; off >>= 1) {
        aff += __shfl_down_sync(FULL, aff, off);
        exc += __shfl_down_sync(FULL, exc, off);
        inh += __shfl_down_sync(FULL, inh, off);
    }
    __shared__ float s_red[3][THREADS_ / 32];
    const int wid = t >> 5, lid = t & 31;
    if (lid == 0) { s_red[0][wid] = aff; s_red[1][wid] = exc; s_red[2][wid] = inh; }
    __syncthreads();

    if (t == 0) {
        float a = 0.f, ee = 0.f, ii = 0.f;
        #pragma unroll
        for (int w = 0; w < THREADS_ / 32; w++) {
            a += s_red[0][w]; ee += s_red[1][w]; ii += s_red[2][w];
        }
        float total = a + GAMMA_E * ee - GAMMA_I * ii;
        float act = fmaxf(total, 0.f);
        #pragma unroll
        for (int c = 0; c < C_; c++)
            out[c * G_ + ij] = act;
    }
}

extern "C" void kernel_launch(void* const* d_in, const int* in_sizes, int n_in,
                              void* d_out, int out_size)
{
    const float* x    = (const float*)d_in[0];
    const float* prev = (const float*)d_in[1];
    const float* aw   = (const float*)d_in[2];
    const float* ew   = (const float*)d_in[3];
    const float* iw   = (const float*)d_in[4];
    const int*   rx   = (const int*)d_in[5];
    const int*   ry   = (const int*)d_in[6];
    float* out = (float*)d_out;

    cortex_kernel<<<G_, THREADS_>>>(x, prev, aw, ew, iw, rx, ry, out);
}

// round 2
// speedup vs baseline: 1.2000x; 1.2000x over previous
#include <cuda_runtime.h>

#define C_   16
#define GX_  36
#define GY_  36
#define RF_  24
#define IMG_ 64
#define G_   (GX_ * GY_)        // 1296
#define GAMMA_E 0.9f
#define GAMMA_I 0.9f

// Partial sums: [c][3][ij]  (aff, p*exc, p*inh), each slot written exactly once
__device__ float g_part[C_ * 3 * G_];

__global__ __launch_bounds__(128, 16)
void cortex_partial(const float* __restrict__ x,
                    const float* __restrict__ prev,
                    const float* __restrict__ aw,
                    const float* __restrict__ ew,
                    const float* __restrict__ iw,
                    const int*   __restrict__ rx,
                    const int*   __restrict__ ry)
{
    const int ij = blockIdx.x;           // 0..1295
    const int c  = blockIdx.y;           // 0..15
    const int i  = ij / GY_;
    const int j  = ij - i * GY_;
    const int t  = threadIdx.x;

    // ---- Lateral row sums (324 float4 per tensor) ----
    const size_t rowbase = (size_t)(c * G_ + ij) * G_;
    const float4* e4 = reinterpret_cast<const float4*>(ew + rowbase);
    const float4* i4 = reinterpret_cast<const float4*>(iw + rowbase);
    float se = 0.f, si = 0.f;
    const int NF4 = G_ / 4;              // 324
    #pragma unroll
    for (int o = t; o < NF4; o += 128) {
        const float4 ve = __ldg(e4 + o);
        const float4 vi = __ldg(i4 + o);
        se += (ve.x + ve.y) + (ve.z + ve.w);
        si += (vi.x + vi.y) + (vi.z + vi.w);
    }

    // ---- Afferent (144 float4) ----
    float aff = 0.f;
    const int rxi = __ldg(rx + i), ryj = __ldg(ry + j);
    const float4* a4 = reinterpret_cast<const float4*>(
        aw + (size_t)(c * G_ + ij) * (RF_ * RF_));
    #pragma unroll
    for (int o = t; o < (RF_ * RF_) / 4; o += 128) {
        const float4 w4 = __ldg(a4 + o);
        const int uv = o * 4;
        const int u  = uv / RF_;
        const int v  = uv - u * RF_;
        const float* xr = x + c * IMG_ * IMG_ + (rxi + u) * IMG_ + (ryj + v);
        aff += w4.x * __ldg(xr + 0) + w4.y * __ldg(xr + 1)
             + w4.z * __ldg(xr + 2) + w4.w * __ldg(xr + 3);
    }

    // ---- Block reduce (128 threads = 4 warps) ----
    const unsigned FULL = 0xFFFFFFFFu;
    #pragma unroll
    for (int off = 16; off > 0; off >>= 1) {
        aff += __shfl_down_sync(FULL, aff, off);
        se  += __shfl_down_sync(FULL, se,  off);
        si  += __shfl_down_sync(FULL, si,  off);
    }
    __shared__ float s_red[3][4];
    const int wid = t >> 5, lid = t & 31;
    if (lid == 0) { s_red[0][wid] = aff; s_red[1][wid] = se; s_red[2][wid] = si; }
    __syncthreads();

    if (t == 0) {
        float a = s_red[0][0] + s_red[0][1] + s_red[0][2] + s_red[0][3];
        float e = s_red[1][0] + s_red[1][1] + s_red[1][2] + s_red[1][3];
        float v = s_red[2][0] + s_red[2][1] + s_red[2][2] + s_red[2][3];
        const float p = __ldg(prev + c * G_ + ij);
        g_part[(c * 3 + 0) * G_ + ij] = a;
        g_part[(c * 3 + 1) * G_ + ij] = p * e;
        g_part[(c * 3 + 2) * G_ + ij] = p * v;
    }
}

__global__ void cortex_finalize(float* __restrict__ out)
{
    const int ij = blockIdx.x * blockDim.x + threadIdx.x;
    if (ij >= G_) return;
    float a = 0.f, e = 0.f, v = 0.f;
    #pragma unroll
    for (int c = 0; c < C_; c++) {
        a += g_part[(c * 3 + 0) * G_ + ij];
        e += g_part[(c * 3 + 1) * G_ + ij];
        v += g_part[(c * 3 + 2) * G_ + ij];
    }
    const float act = fmaxf(a + GAMMA_E * e - GAMMA_I * v, 0.f);
    #pragma unroll
    for (int c = 0; c < C_; c++)
        out[c * G_ + ij] = act;
}

extern "C" void kernel_launch(void* const* d_in, const int* in_sizes, int n_in,
                              void* d_out, int out_size)
{
    const float* x    = (const float*)d_in[0];
    const float* prev = (const float*)d_in[1];
    const float* aw   = (const float*)d_in[2];
    const float* ew   = (const float*)d_in[3];
    const float* iw   = (const float*)d_in[4];
    const int*   rx   = (const int*)d_in[5];
    const int*   ry   = (const int*)d_in[6];
    float* out = (float*)d_out;

    dim3 grid(G_, C_);
    cortex_partial<<<grid, 128>>>(x, prev, aw, ew, iw, rx, ry);
    cortex_finalize<<<(G_ + 255) / 256, 256>>>(out);
}

// round 3
// speedup vs baseline: 1.2275x; 1.0230x over previous
#include <cuda_runtime.h>

#define C_   16
#define GX_  36
#define GY_  36
#define RF_  24
#define IMG_ 64
#define G_   (GX_ * GY_)        // 1296
#define GAMMA_E 0.9f
#define GAMMA_I 0.9f

// Partial sums: [c][3][ij]  (aff, p*exc, p*inh), each slot written exactly once
__device__ float    g_part[C_ * 3 * G_];
__device__ unsigned g_cnt[G_];           // zero-initialized; reset by finalizer

__device__ __forceinline__ float4 ldcs4(const float4* p) {
    return __ldcs(p);                    // evict-first streaming load
}

__global__ __launch_bounds__(128, 16)
void cortex_fused(const float* __restrict__ x,
                  const float* __restrict__ prev,
                  const float* __restrict__ aw,
                  const float* __restrict__ ew,
                  const float* __restrict__ iw,
                  const int*   __restrict__ rx,
                  const int*   __restrict__ ry,
                  float*       __restrict__ out)
{
    const int ij = blockIdx.x;           // 0..1295
    const int c  = blockIdx.y;           // 0..15
    const int i  = ij / GY_;
    const int j  = ij - i * GY_;
    const int t  = threadIdx.x;

    // ---- Lateral row sums (324 float4 per tensor, streamed once) ----
    const size_t rowbase = (size_t)(c * G_ + ij) * G_;
    const float4* e4 = reinterpret_cast<const float4*>(ew + rowbase);
    const float4* i4 = reinterpret_cast<const float4*>(iw + rowbase);
    float se = 0.f, si = 0.f;
    const int NF4 = G_ / 4;              // 324
    #pragma unroll
    for (int o = t; o < NF4; o += 128) {
        const float4 ve = ldcs4(e4 + o);
        const float4 vi = ldcs4(i4 + o);
        se += (ve.x + ve.y) + (ve.z + ve.w);
        si += (vi.x + vi.y) + (vi.z + vi.w);
    }

    // ---- Afferent (144 float4, streamed once; x is L2-resident) ----
    float aff = 0.f;
    const int rxi = __ldg(rx + i), ryj = __ldg(ry + j);
    const float4* a4 = reinterpret_cast<const float4*>(
        aw + (size_t)(c * G_ + ij) * (RF_ * RF_));
    #pragma unroll
    for (int o = t; o < (RF_ * RF_) / 4; o += 128) {
        const float4 w4 = ldcs4(a4 + o);
        const int uv = o * 4;
        const int u  = uv / RF_;
        const int v  = uv - u * RF_;
        const float* xr = x + c * IMG_ * IMG_ + (rxi + u) * IMG_ + (ryj + v);
        aff += w4.x * __ldg(xr + 0) + w4.y * __ldg(xr + 1)
             + w4.z * __ldg(xr + 2) + w4.w * __ldg(xr + 3);
    }

    // ---- Block reduce (128 threads = 4 warps) ----
    const unsigned FULL = 0xFFFFFFFFu;
    #pragma unroll
    for (int off = 16; off > 0; off >>= 1) {
        aff += __shfl_down_sync(FULL, aff, off);
        se  += __shfl_down_sync(FULL, se,  off);
        si  += __shfl_down_sync(FULL, si,  off);
    }
    __shared__ float s_red[3][4];
    const int wid = t >> 5, lid = t & 31;
    if (lid == 0) { s_red[0][wid] = aff; s_red[1][wid] = se; s_red[2][wid] = si; }
    __syncthreads();

    if (t != 0) return;

    {
        float a = s_red[0][0] + s_red[0][1] + s_red[0][2] + s_red[0][3];
        float e = s_red[1][0] + s_red[1][1] + s_red[1][2] + s_red[1][3];
        float v = s_red[2][0] + s_red[2][1] + s_red[2][2] + s_red[2][3];
        const float p = __ldg(prev + c * G_ + ij);
        g_part[(c * 3 + 0) * G_ + ij] = a;
        g_part[(c * 3 + 1) * G_ + ij] = p * e;
        g_part[(c * 3 + 2) * G_ + ij] = p * v;
    }
    __threadfence();

    // Last CTA for this ij performs the finalize (deterministic fixed-order sum)
    const unsigned ticket = atomicAdd(&g_cnt[ij], 1u);
    if (ticket == C_ - 1) {
        float a = 0.f, e = 0.f, v = 0.f;
        #pragma unroll
        for (int cc = 0; cc < C_; cc++) {
            a += __ldcg(&g_part[(cc * 3 + 0) * G_ + ij]);
            e += __ldcg(&g_part[(cc * 3 + 1) * G_ + ij]);
            v += __ldcg(&g_part[(cc * 3 + 2) * G_ + ij]);
        }
        const float act = fmaxf(a + GAMMA_E * e - GAMMA_I * v, 0.f);
        #pragma unroll
        for (int cc = 0; cc < C_; cc++)
            out[cc * G_ + ij] = act;
        g_cnt[ij] = 0;                   // reset for next graph replay
    }
}

extern "C" void kernel_launch(void* const* d_in, const int* in_sizes, int n_in,
                              void* d_out, int out_size)
{
    const float* x    = (const float*)d_in[0];
    const float* prev = (const float*)d_in[1];
    const float* aw   = (const float*)d_in[2];
    const float* ew   = (const float*)d_in[3];
    const float* iw   = (const float*)d_in[4];
    const int*   rx   = (const int*)d_in[5];
    const int*   ry   = (const int*)d_in[6];
    float* out = (float*)d_out;

    dim3 grid(G_, C_);
    cortex_fused<<<grid, 128>>>(x, prev, aw, ew, iw, rx, ry, out);
}

// round 4
// speedup vs baseline: 1.2581x; 1.0249x over previous
#include <cuda_runtime.h>

#define C_   16
#define GX_  36
#define GY_  36
#define RF_  24
#define IMG_ 64
#define G_   (GX_ * GY_)        // 1296
#define GAMMA_E 0.9f
#define GAMMA_I 0.9f

// Combined partial per (c,ij): aff + ge*p*exc - gi*p*inh. Written exactly once.
__device__ float    g_part[C_ * G_];
__device__ unsigned g_cnt[G_];           // zero-initialized; reset by finalizer

__global__ __launch_bounds__(128, 16)
void cortex_fused(const float* __restrict__ x,
                  const float* __restrict__ prev,
                  const float* __restrict__ aw,
                  const float* __restrict__ ew,
                  const float* __restrict__ iw,
                  const int*   __restrict__ rx,
                  const int*   __restrict__ ry,
                  float*       __restrict__ out)
{
    const int ij = blockIdx.x;           // 0..1295
    const int c  = blockIdx.y;           // 0..15
    const int i  = ij / GY_;
    const int j  = ij - i * GY_;
    const int t  = threadIdx.x;

    // ---- Lateral row sums (324 float4 per tensor, streamed once) ----
    const size_t rowbase = (size_t)(c * G_ + ij) * G_;
    const float4* e4 = reinterpret_cast<const float4*>(ew + rowbase);
    const float4* i4 = reinterpret_cast<const float4*>(iw + rowbase);
    float se = 0.f, si = 0.f;
    const int NF4 = G_ / 4;              // 324
    #pragma unroll
    for (int o = t; o < NF4; o += 128) {
        const float4 ve = __ldcs(e4 + o);
        const float4 vi = __ldcs(i4 + o);
        se += (ve.x + ve.y) + (ve.z + ve.w);
        si += (vi.x + vi.y) + (vi.z + vi.w);
    }

    // ---- Afferent (144 float4, streamed once; x is L1/L2-resident) ----
    float aff = 0.f;
    const int rxi = __ldg(rx + i), ryj = __ldg(ry + j);
    const float4* a4 = reinterpret_cast<const float4*>(
        aw + (size_t)(c * G_ + ij) * (RF_ * RF_));
    #pragma unroll
    for (int o = t; o < (RF_ * RF_) / 4; o += 128) {
        const float4 w4 = __ldcs(a4 + o);
        const int uv = o * 4;
        const int u  = uv / RF_;
        const int v  = uv - u * RF_;
        const float* xr = x + c * IMG_ * IMG_ + (rxi + u) * IMG_ + (ryj + v);
        aff += w4.x * __ldg(xr + 0) + w4.y * __ldg(xr + 1)
             + w4.z * __ldg(xr + 2) + w4.w * __ldg(xr + 3);
    }

    // ---- Block reduce (128 threads = 4 warps) ----
    const unsigned FULL = 0xFFFFFFFFu;
    #pragma unroll
    for (int off = 16; off > 0; off >>= 1) {
        aff += __shfl_down_sync(FULL, aff, off);
        se  += __shfl_down_sync(FULL, se,  off);
        si  += __shfl_down_sync(FULL, si,  off);
    }
    __shared__ float s_red[3][4];
    const int wid = t >> 5, lid = t & 31;
    if (lid == 0) { s_red[0][wid] = aff; s_red[1][wid] = se; s_red[2][wid] = si; }
    __syncthreads();

    if (t != 0) return;

    {
        const float a = s_red[0][0] + s_red[0][1] + s_red[0][2] + s_red[0][3];
        const float e = s_red[1][0] + s_red[1][1] + s_red[1][2] + s_red[1][3];
        const float v = s_red[2][0] + s_red[2][1] + s_red[2][2] + s_red[2][3];
        const float p = __ldg(prev + c * G_ + ij);
        g_part[c * G_ + ij] = a + GAMMA_E * (p * e) - GAMMA_I * (p * v);
    }

    // Release-ordered ticket: orders the g_part store above without MEMBAR/L1 flush.
    unsigned ticket;
    asm volatile("atom.acq_rel.gpu.global.add.u32 %0, [%1], %2;"
                 : "=r"(ticket)
                 : "l"(&g_cnt[ij]), "r"(1u)
                 : "memory");

    if (ticket == C_ - 1) {
        float tot = 0.f;
        #pragma unroll
        for (int cc = 0; cc < C_; cc++)
            tot += __ldcg(&g_part[cc * G_ + ij]);
        const float act = fmaxf(tot, 0.f);
        #pragma unroll
        for (int cc = 0; cc < C_; cc++)
            out[cc * G_ + ij] = act;
        g_cnt[ij] = 0;                   // reset for next graph replay
    }
}

extern "C" void kernel_launch(void* const* d_in, const int* in_sizes, int n_in,
                              void* d_out, int out_size)
{
    const float* x    = (const float*)d_in[0];
    const float* prev = (const float*)d_in[1];
    const float* aw   = (const float*)d_in[2];
    const float* ew   = (const float*)d_in[3];
    const float* iw   = (const float*)d_in[4];
    const int*   rx   = (const int*)d_in[5];
    const int*   ry   = (const int*)d_in[6];
    float* out = (float*)d_out;

    dim3 grid(G_, C_);
    cortex_fused<<<grid, 128>>>(x, prev, aw, ew, iw, rx, ry, out);
}

// round 5
// speedup vs baseline: 1.3146x; 1.0449x over previous
#include <cuda_runtime.h>

#define C_   16
#define GX_  36
#define GY_  36
#define RF_  24
#define IMG_ 64
#define G_   (GX_ * GY_)        // 1296
#define GAMMA_E 0.9f
#define GAMMA_I 0.9f

// Combined partial per (ij,c): aff + ge*p*exc - gi*p*inh.
// Layout [ij][c] so finalize reads 16 contiguous floats per ij.
__device__ float g_part[G_ * C_];

__global__ __launch_bounds__(128, 16)
void cortex_partial(const float* __restrict__ x,
                    const float* __restrict__ prev,
                    const float* __restrict__ aw,
                    const float* __restrict__ ew,
                    const float* __restrict__ iw,
                    const int*   __restrict__ rx,
                    const int*   __restrict__ ry)
{
    const int ij = blockIdx.x;           // 0..1295
    const int c  = blockIdx.y;           // 0..15
    const int i  = ij / GY_;
    const int j  = ij - i * GY_;
    const int t  = threadIdx.x;

    // ---- Lateral row sums (324 float4 per tensor, streamed once) ----
    const size_t rowbase = (size_t)(c * G_ + ij) * G_;
    const float4* e4 = reinterpret_cast<const float4*>(ew + rowbase);
    const float4* i4 = reinterpret_cast<const float4*>(iw + rowbase);
    float se = 0.f, si = 0.f;
    const int NF4 = G_ / 4;              // 324
    #pragma unroll
    for (int o = t; o < NF4; o += 128) {
        const float4 ve = __ldcs(e4 + o);
        const float4 vi = __ldcs(i4 + o);
        se += (ve.x + ve.y) + (ve.z + ve.w);
        si += (vi.x + vi.y) + (vi.z + vi.w);
    }

    // ---- Afferent (144 float4, streamed once; x is L1/L2-resident) ----
    float aff = 0.f;
    const int rxi = __ldg(rx + i), ryj = __ldg(ry + j);
    const float4* a4 = reinterpret_cast<const float4*>(
        aw + (size_t)(c * G_ + ij) * (RF_ * RF_));
    #pragma unroll
    for (int o = t; o < (RF_ * RF_) / 4; o += 128) {
        const float4 w4 = __ldcs(a4 + o);
        const int uv = o * 4;
        const int u  = uv / RF_;
        const int v  = uv - u * RF_;
        const float* xr = x + c * IMG_ * IMG_ + (rxi + u) * IMG_ + (ryj + v);
        aff += w4.x * __ldg(xr + 0) + w4.y * __ldg(xr + 1)
             + w4.z * __ldg(xr + 2) + w4.w * __ldg(xr + 3);
    }

    // ---- Block reduce (128 threads = 4 warps) ----
    const unsigned FULL = 0xFFFFFFFFu;
    #pragma unroll
    for (int off = 16; off > 0; off >>= 1) {
        aff += __shfl_down_sync(FULL, aff, off);
        se  += __shfl_down_sync(FULL, se,  off);
        si  += __shfl_down_sync(FULL, si,  off);
    }
    __shared__ float s_red[3][4];
    const int wid = t >> 5, lid = t & 31;
    if (lid == 0) { s_red[0][wid] = aff; s_red[1][wid] = se; s_red[2][wid] = si; }
    __syncthreads();

    if (t == 0) {
        const float a = s_red[0][0] + s_red[0][1] + s_red[0][2] + s_red[0][3];
        const float e = s_red[1][0] + s_red[1][1] + s_red[1][2] + s_red[1][3];
        const float v = s_red[2][0] + s_red[2][1] + s_red[2][2] + s_red[2][3];
        const float p = __ldg(prev + c * G_ + ij);
        g_part[ij * C_ + c] = a + GAMMA_E * (p * e) - GAMMA_I * (p * v);
    }
}

// One warp per ij: coalesced 64B load of the 16 partials, shuffle reduce,
// relu, broadcast-store to the 16 output channels.
__global__ __launch_bounds__(256)
void cortex_finalize(float* __restrict__ out)
{
    const int gw   = (blockIdx.x * blockDim.x + threadIdx.x) >> 5;  // warp id
    const int lane = threadIdx.x & 31;
    if (gw >= G_) return;

    float v = (lane < C_) ? g_part[gw * C_ + lane] : 0.f;
    const unsigned FULL = 0xFFFFFFFFu;
    v += __shfl_down_sync(FULL, v, 8);
    v += __shfl_down_sync(FULL, v, 4);
    v += __shfl_down_sync(FULL, v, 2);
    v += __shfl_down_sync(FULL, v, 1);
    const float act = fmaxf(__shfl_sync(FULL, v, 0), 0.f);
    if (lane < C_)
        out[lane * G_ + gw] = act;
}

extern "C" void kernel_launch(void* const* d_in, const int* in_sizes, int n_in,
                              void* d_out, int out_size)
{
    const float* x    = (const float*)d_in[0];
    const float* prev = (const float*)d_in[1];
    const float* aw   = (const float*)d_in[2];
    const float* ew   = (const float*)d_in[3];
    const float* iw   = (const float*)d_in[4];
    const int*   rx   = (const int*)d_in[5];
    const int*   ry   = (const int*)d_in[6];
    float* out = (float*)d_out;

    dim3 grid(G_, C_);
    cortex_partial<<<grid, 128>>>(x, prev, aw, ew, iw, rx, ry);

    const int warps_per_cta = 256 / 32;
    const int n_cta = (G_ + warps_per_cta - 1) / warps_per_cta;   // 162
    cortex_finalize<<<n_cta, 256>>>(out);
}

// round 6
// speedup vs baseline: 1.3391x; 1.0186x over previous
#include <cuda_runtime.h>

#define C_   16
#define GX_  36
#define GY_  36
#define RF_  24
#define IMG_ 64
#define G_   (GX_ * GY_)        // 1296
#define GAMMA_E 0.9f
#define GAMMA_I 0.9f

// Combined partial per (ij,c): aff + ge*p*exc - gi*p*inh.
// Layout [ij][c] so finalize reads 16 contiguous floats per ij.
__device__ float g_part[G_ * C_];

__global__ __launch_bounds__(128, 16)
void cortex_partial(const float* __restrict__ x,
                    const float* __restrict__ prev,
                    const float* __restrict__ aw,
                    const float* __restrict__ ew,
                    const float* __restrict__ iw,
                    const int*   __restrict__ rx,
                    const int*   __restrict__ ry)
{
    const int ij = blockIdx.x;           // 0..1295
    const int c  = blockIdx.y;           // 0..15
    const int i  = ij / GY_;
    const int j  = ij - i * GY_;
    const int t  = threadIdx.x;

    // ---- Lateral row sums (324 float4 per tensor, streamed once) ----
    const size_t rowbase = (size_t)(c * G_ + ij) * G_;
    const float4* e4 = reinterpret_cast<const float4*>(ew + rowbase);
    const float4* i4 = reinterpret_cast<const float4*>(iw + rowbase);
    float se = 0.f, si = 0.f;
    const int NF4 = G_ / 4;              // 324
    #pragma unroll
    for (int o = t; o < NF4; o += 128) {
        const float4 ve = __ldcs(e4 + o);
        const float4 vi = __ldcs(i4 + o);
        se += (ve.x + ve.y) + (ve.z + ve.w);
        si += (vi.x + vi.y) + (vi.z + vi.w);
    }

    // ---- Afferent (144 float4, streamed once; x is L1/L2-resident) ----
    float aff = 0.f;
    const int rxi = __ldg(rx + i), ryj = __ldg(ry + j);
    const float4* a4 = reinterpret_cast<const float4*>(
        aw + (size_t)(c * G_ + ij) * (RF_ * RF_));
    #pragma unroll
    for (int o = t; o < (RF_ * RF_) / 4; o += 128) {
        const float4 w4 = __ldcs(a4 + o);
        const int uv = o * 4;
        const int u  = uv / RF_;
        const int v  = uv - u * RF_;
        const float* xr = x + c * IMG_ * IMG_ + (rxi + u) * IMG_ + (ryj + v);
        aff += w4.x * __ldg(xr + 0) + w4.y * __ldg(xr + 1)
             + w4.z * __ldg(xr + 2) + w4.w * __ldg(xr + 3);
    }

    // ---- Block reduce (128 threads = 4 warps) ----
    const unsigned FULL = 0xFFFFFFFFu;
    #pragma unroll
    for (int off = 16; off > 0; off >>= 1) {
        aff += __shfl_down_sync(FULL, aff, off);
        se  += __shfl_down_sync(FULL, se,  off);
        si  += __shfl_down_sync(FULL, si,  off);
    }
    __shared__ float s_red[3][4];
    const int wid = t >> 5, lid = t & 31;
    if (lid == 0) { s_red[0][wid] = aff; s_red[1][wid] = se; s_red[2][wid] = si; }
    __syncthreads();

    if (t == 0) {
        const float a = s_red[0][0] + s_red[0][1] + s_red[0][2] + s_red[0][3];
        const float e = s_red[1][0] + s_red[1][1] + s_red[1][2] + s_red[1][3];
        const float v = s_red[2][0] + s_red[2][1] + s_red[2][2] + s_red[2][3];
        const float p = __ldg(prev + c * G_ + ij);
        g_part[ij * C_ + c] = a + GAMMA_E * (p * e) - GAMMA_I * (p * v);
    }

    // Allow the dependent (finalize) grid to start launching as early as HW permits.
    asm volatile("griddepcontrol.launch_dependents;");
}

// One warp per ij: coalesced 64B load of the 16 partials, shuffle reduce,
// relu, broadcast-store to the 16 output channels. Launched with PDL so its
// scheduling overlaps the partial kernel's tail.
__global__ __launch_bounds__(256)
void cortex_finalize(float* __restrict__ out)
{
    const int gw   = (blockIdx.x * blockDim.x + threadIdx.x) >> 5;  // warp id
    const int lane = threadIdx.x & 31;

    // Wait until all memory from cortex_partial is visible.
    asm volatile("griddepcontrol.wait;" ::: "memory");

    if (gw >= G_) return;

    float v = (lane < C_) ? g_part[gw * C_ + lane] : 0.f;
    const unsigned FULL = 0xFFFFFFFFu;
    v += __shfl_down_sync(FULL, v, 8);
    v += __shfl_down_sync(FULL, v, 4);
    v += __shfl_down_sync(FULL, v, 2);
    v += __shfl_down_sync(FULL, v, 1);
    const float act = fmaxf(__shfl_sync(FULL, v, 0), 0.f);
    if (lane < C_)
        out[lane * G_ + gw] = act;
}

extern "C" void kernel_launch(void* const* d_in, const int* in_sizes, int n_in,
                              void* d_out, int out_size)
{
    const float* x    = (const float*)d_in[0];
    const float* prev = (const float*)d_in[1];
    const float* aw   = (const float*)d_in[2];
    const float* ew   = (const float*)d_in[3];
    const float* iw   = (const float*)d_in[4];
    const int*   rx   = (const int*)d_in[5];
    const int*   ry   = (const int*)d_in[6];
    float* out = (float*)d_out;

    dim3 grid(G_, C_);
    cortex_partial<<<grid, 128>>>(x, prev, aw, ew, iw, rx, ry);

    // Finalize with programmatic dependent launch (overlaps partial's tail).
    const int warps_per_cta = 256 / 32;
    const int n_cta = (G_ + warps_per_cta - 1) / warps_per_cta;   // 162

    cudaLaunchConfig_t cfg = {};
    cfg.gridDim  = dim3(n_cta, 1, 1);
    cfg.blockDim = dim3(256, 1, 1);
    cfg.dynamicSmemBytes = 0;
    cudaLaunchAttribute attrs[1];
    attrs[0].id = cudaLaunchAttributeProgrammaticStreamSerialization;
    attrs[0].val.programmaticStreamSerializationAllowed = 1;
    cfg.attrs = attrs;
    cfg.numAttrs = 1;
    cudaLaunchKernelEx(&cfg, cortex_finalize, out);
}